// round 2
// baseline (speedup 1.0000x reference)
#include <cuda_runtime.h>

#define B_   4
#define C_   256
#define CR_  64
#define H_   64
#define W_   64
#define HW_  4096
#define KK_  49
#define G_   16
#define GC_  16

// scratch for x = relu(bn(w1 @ guide)) : [B, CR, H, W]
__device__ float g_x[B_ * CR_ * HW_];

// ---------------------------------------------------------------------------
// Kernel 1: x[b,r,hw] = relu( inv[r] * (sum_c w1[r,c]*guide[b,c,hw]) + bias[r] )
// block: 256 threads -> 128 pixels x 64 r.  grid: (4096/128, B)
// ---------------------------------------------------------------------------
__global__ __launch_bounds__(256) void k1_compute_x(
    const float* __restrict__ guide,
    const float* __restrict__ w1,
    const float* __restrict__ gamma,
    const float* __restrict__ beta,
    const float* __restrict__ mean,
    const float* __restrict__ var)
{
    __shared__ float inv_s[CR_];
    __shared__ float bias_s[CR_];
    __shared__ float gtile[16][128];   // [c_chunk][px]
    __shared__ float w1t[16][CR_];     // [c_chunk][r], BN-scale folded

    const int t    = threadIdx.x;
    const int b    = blockIdx.y;
    const int pix0 = blockIdx.x * 128;

    if (t < CR_) {
        float iv  = gamma[t] * rsqrtf(var[t] + 1e-5f);
        inv_s[t]  = iv;
        bias_s[t] = beta[t] - mean[t] * iv;
    }
    __syncthreads();

    const int pxg = t & 31;     // pixel group lane
    const int rg  = t >> 5;     // 0..7 -> 8 rows each

    float acc[4][8];
    #pragma unroll
    for (int i = 0; i < 4; i++)
        #pragma unroll
        for (int j = 0; j < 8; j++) acc[i][j] = 0.f;

    for (int c0 = 0; c0 < C_; c0 += 16) {
        // load guide tile: 16 x 128, coalesced
        #pragma unroll
        for (int j = 0; j < 8; j++) {
            int idx = t + 256 * j;
            int cc = idx >> 7, px = idx & 127;
            gtile[cc][px] = guide[(b * C_ + c0 + cc) * HW_ + pix0 + px];
        }
        // load w1 tile (fold inv): w1t[cc][r] = w1[r][c0+cc]*inv[r]
        #pragma unroll
        for (int j = 0; j < 4; j++) {
            int idx = t + 256 * j;
            int r = idx >> 4, cc = idx & 15;
            w1t[cc][r] = w1[r * C_ + c0 + cc] * inv_s[r];
        }
        __syncthreads();

        #pragma unroll
        for (int cc = 0; cc < 16; cc++) {
            float g0 = gtile[cc][pxg];
            float g1 = gtile[cc][pxg + 32];
            float g2 = gtile[cc][pxg + 64];
            float g3 = gtile[cc][pxg + 96];
            #pragma unroll
            for (int rr = 0; rr < 8; rr++) {
                float w = w1t[cc][rg * 8 + rr];   // broadcast within warp
                acc[0][rr] += w * g0;
                acc[1][rr] += w * g1;
                acc[2][rr] += w * g2;
                acc[3][rr] += w * g3;
            }
        }
        __syncthreads();
    }

    #pragma unroll
    for (int rr = 0; rr < 8; rr++) {
        int r = rg * 8 + rr;
        float bsv = bias_s[r];
        #pragma unroll
        for (int i = 0; i < 4; i++) {
            float v = fmaxf(acc[i][rr] + bsv, 0.f);
            g_x[(b * CR_ + r) * HW_ + pix0 + pxg + 32 * i] = v;
        }
    }
}

// ---------------------------------------------------------------------------
// Kernel 2: fused per-pixel dynamic-kernel GEMM (w2 @ x + b2) + involution
// aggregation + residual. block = 8x8 pixel tile, 256 threads. grid (8,8,B).
// ---------------------------------------------------------------------------

// dynamic smem layout (floats):
#define XT_OFF   0                     // [64 r][64 px]
#define W2G_OFF  4096                  // [49 k][65]  (pad 65)
#define WSM_OFF  (4096 + 3188)        // 7284: [64 px][51] (pad 51, odd)
#define FH_OFF   (7284 + 3264)        // 10548: [16 ch][14 rows][16] (row pad 16)
#define B2S_OFF  (10548 + 3584)       // 14132: [49]
#define SMEM2_FLOATS 14184
#define SMEM2_BYTES  (SMEM2_FLOATS * 4)

__global__ __launch_bounds__(256) void k2_fused(
    const float* __restrict__ feat,
    const float* __restrict__ w2,
    const float* __restrict__ b2,
    float* __restrict__ out)
{
    extern __shared__ float sm[];
    float* xt  = sm + XT_OFF;
    float* w2g = sm + W2G_OFF;
    float* wsm = sm + WSM_OFF;
    float* fh  = sm + FH_OFF;
    float* b2s = sm + B2S_OFF;

    const int t   = threadIdx.x;
    const int b   = blockIdx.z;
    const int tx0 = blockIdx.x * 8;
    const int ty0 = blockIdx.y * 8;

    // load x tile: xt[r][p], p = py*8 + px
    #pragma unroll
    for (int j = 0; j < 16; j++) {
        int idx = t + 256 * j;
        int r = idx >> 6, p = idx & 63;
        xt[r * 64 + p] =
            g_x[(b * CR_ + r) * HW_ + (ty0 + (p >> 3)) * W_ + tx0 + (p & 7)];
    }

    // weight-phase thread tile: 4 px x 3 k
    const int pxq = t & 15;        // -> pixels pxq*4 .. pxq*4+3
    const int kg  = t >> 4;        // 0..15 -> k = 3*kg .. 3*kg+2
    const int k0  = 3 * kg;

    // aggregation thread tile: 2 px x 2 ch
    const int p2  = t & 31;        // -> pixels 2*p2, 2*p2+1
    const int cp  = t >> 5;        // -> channels 2*cp, 2*cp+1
    const int pb  = 2 * p2;
    const int py  = pb >> 3;
    const int pxx = pb & 7;        // even

    for (int g = 0; g < G_; g++) {
        // ---- load w2 group slice (3136 contiguous floats), pad-stride 65 ----
        #pragma unroll
        for (int j = 0; j < 13; j++) {
            int idx = t + 256 * j;
            if (idx < KK_ * CR_) {
                int k = idx >> 6, r = idx & 63;
                w2g[k * 65 + r] = w2[g * (KK_ * CR_) + idx];
            }
        }
        if (t < KK_) b2s[t] = b2[g * KK_ + t];

        // ---- load feature halo: 16 ch x 14 x 14 (zero pad at borders) ----
        #pragma unroll
        for (int j = 0; j < 13; j++) {
            int idx = t + 256 * j;
            if (idx < 16 * 196) {
                int cc = idx / 196;
                int r2 = idx - cc * 196;
                int iy = r2 / 14, ix = r2 - iy * 14;
                int gy = ty0 + iy - 3, gx = tx0 + ix - 3;
                float v = 0.f;
                if ((unsigned)gy < 64u && (unsigned)gx < 64u)
                    v = feat[(b * C_ + g * GC_ + cc) * HW_ + gy * W_ + gx];
                fh[cc * 224 + iy * 16 + ix] = v;
            }
        }
        __syncthreads();

        // ---- phase 1: weight[px][k] = w2g[k] . xt[:,px] + b2 ----
        {
            float acc[3][4];
            #pragma unroll
            for (int j = 0; j < 3; j++)
                #pragma unroll
                for (int i = 0; i < 4; i++) acc[j][i] = 0.f;

            #pragma unroll 4
            for (int r = 0; r < 64; r++) {
                float4 xv = *(const float4*)&xt[r * 64 + pxq * 4];
                #pragma unroll
                for (int j = 0; j < 3; j++) {
                    float w = w2g[(k0 + j) * 65 + r];
                    acc[j][0] += w * xv.x;
                    acc[j][1] += w * xv.y;
                    acc[j][2] += w * xv.z;
                    acc[j][3] += w * xv.w;
                }
            }
            #pragma unroll
            for (int j = 0; j < 3; j++) {
                float bv = b2s[k0 + j];
                #pragma unroll
                for (int i = 0; i < 4; i++)
                    wsm[(pxq * 4 + i) * 51 + (k0 + j)] = acc[j][i] + bv;
            }
            // peeled tap k = 48 (one thread per pixel)
            if (t < 64) {
                float a = 0.f;
                #pragma unroll 8
                for (int r = 0; r < 64; r++)
                    a += w2g[48 * 65 + r] * xt[r * 64 + t];
                wsm[t * 51 + 48] = a + b2s[48];
            }
        }
        __syncthreads();

        // ---- phase 2: out[px][c] = sum_k w[px][k] * fh[c][py+ky][pxx+kx] ----
        {
            float oacc[2][2] = {{0.f, 0.f}, {0.f, 0.f}};
            #pragma unroll
            for (int ky = 0; ky < 7; ky++) {
                float wk0[7], wk1[7];
                #pragma unroll
                for (int kx = 0; kx < 7; kx++) {
                    wk0[kx] = wsm[pb * 51 + ky * 7 + kx];
                    wk1[kx] = wsm[(pb + 1) * 51 + ky * 7 + kx];
                }
                #pragma unroll
                for (int c = 0; c < 2; c++) {
                    const float* frow =
                        &fh[(cp * 2 + c) * 224 + (py + ky) * 16 + pxx];
                    float2 f0 = *(const float2*)(frow);
                    float2 f1 = *(const float2*)(frow + 2);
                    float2 f2 = *(const float2*)(frow + 4);
                    float2 f3 = *(const float2*)(frow + 6);
                    float e[8] = {f0.x, f0.y, f1.x, f1.y,
                                  f2.x, f2.y, f3.x, f3.y};
                    #pragma unroll
                    for (int kx = 0; kx < 7; kx++) {
                        oacc[0][c] += wk0[kx] * e[kx];
                        oacc[1][c] += wk1[kx] * e[kx + 1];
                    }
                }
            }
            // residual (center of halo) + store
            #pragma unroll
            for (int c = 0; c < 2; c++) {
                int cc = cp * 2 + c;
                int ch = g * GC_ + cc;
                #pragma unroll
                for (int i = 0; i < 2; i++) {
                    float v = oacc[i][c] +
                              fh[cc * 224 + (py + 3) * 16 + (pxx + i + 3)];
                    out[(b * C_ + ch) * HW_ + (ty0 + py) * W_ + tx0 + pxx + i] = v;
                }
            }
        }
        __syncthreads();   // protect w2g/fh/wsm before next group
    }
}

// ---------------------------------------------------------------------------
extern "C" void kernel_launch(void* const* d_in, const int* in_sizes, int n_in,
                              void* d_out, int out_size)
{
    const float* feat  = (const float*)d_in[0];
    const float* guide = (const float*)d_in[1];
    const float* w1    = (const float*)d_in[2];
    const float* gamma = (const float*)d_in[3];
    const float* beta  = (const float*)d_in[4];
    const float* mean  = (const float*)d_in[5];
    const float* var   = (const float*)d_in[6];
    const float* w2    = (const float*)d_in[7];
    const float* b2    = (const float*)d_in[8];
    float* out = (float*)d_out;

    cudaFuncSetAttribute(k2_fused,
                         cudaFuncAttributeMaxDynamicSharedMemorySize,
                         SMEM2_BYTES);

    k1_compute_x<<<dim3(32, B_), 256>>>(guide, w1, gamma, beta, mean, var);
    k2_fused<<<dim3(8, 8, B_), 256, SMEM2_BYTES>>>(feat, w2, b2, out);
}